// round 3
// baseline (speedup 1.0000x reference)
#include <cuda_runtime.h>
#include <cuda_bf16.h>

#define BBATCH 16
#define NNODE  2048
#define CDIM   64
#define HDIM   128
#define KNEIGH 16
#define NT     (BBATCH*NNODE)        /* 32768 nodes  */
#define EDGES  (NT*KNEIGH)           /* 524288 edges */
#define BN_EPS 1e-5f
#define LDW    132                   /* smem tile pitch (floats): 16B-aligned, 4-way max conflicts */

typedef unsigned long long ull;

// ---------------------------------------------------------------------------
// Static device scratch (no runtime allocation allowed)
// ---------------------------------------------------------------------------
__device__ float g_sq[NT];
__device__ float g_d2[(size_t)BBATCH * NNODE * NNODE];        // 256 MB
__device__ int   g_idx[EDGES];                                 // global neighbor idx
__device__ float g_p[2][(size_t)NT * HDIM];
__device__ float g_q[2][(size_t)NT * HDIM];
__device__ float g_bn1_sum[2][HDIM], g_bn1_sq[2][HDIM];
__device__ float g_a1[2][HDIM], g_c1[2][HDIM];
__device__ float g_aggmax[2][(size_t)NT * HDIM];
__device__ float g_aggmin[2][(size_t)NT * HDIM];
__device__ float g_bn2_sum[2][HDIM], g_bn2_sq[2][HDIM];
__device__ float g_a2[2][HDIM], g_c2[2][HDIM];
__device__ float g_hF[(size_t)NT * HDIM];
__device__ float g_bnF_sum[HDIM], g_bnF_sq[HDIM];
__device__ float g_aF[HDIM], g_cF[HDIM];

// ---------------------------------------------------------------------------
// f32x2 packed-FMA helpers (sm_100+ PTX; FFMA2 is PTX-only per SASS quickref)
// ---------------------------------------------------------------------------
__device__ __forceinline__ ull pk2(float lo, float hi) {
    ull r; asm("mov.b64 %0, {%1, %2};" : "=l"(r) : "f"(lo), "f"(hi)); return r;
}
__device__ __forceinline__ void fma2(ull &d, ull a, ull b) {
    asm("fma.rn.f32x2 %0, %1, %2, %0;" : "+l"(d) : "l"(a), "l"(b));
}
__device__ __forceinline__ float2 up2(ull v) {
    float2 f; asm("mov.b64 {%0, %1}, %2;" : "=f"(f.x), "=f"(f.y) : "l"(v)); return f;
}

// 8x8 micro-tile step: A k-major [kk][row], B k-major [kk][col], acc packed pairs along cols
__device__ __forceinline__ void micro_step(const float* __restrict__ Arow,
                                           const float* __restrict__ Brow,
                                           int ty8, int tx8, ull acc[8][4]) {
    float4 a0 = *(const float4*)(Arow + ty8);
    float4 a1 = *(const float4*)(Arow + ty8 + 4);
    float4 b0 = *(const float4*)(Brow + tx8);
    float4 b1 = *(const float4*)(Brow + tx8 + 4);
    ull bv0 = pk2(b0.x, b0.y), bv1 = pk2(b0.z, b0.w);
    ull bv2 = pk2(b1.x, b1.y), bv3 = pk2(b1.z, b1.w);
    float av[8] = {a0.x, a0.y, a0.z, a0.w, a1.x, a1.y, a1.z, a1.w};
#pragma unroll
    for (int i = 0; i < 8; i++) {
        ull ai = pk2(av[i], av[i]);
        fma2(acc[i][0], ai, bv0);
        fma2(acc[i][1], ai, bv1);
        fma2(acc[i][2], ai, bv2);
        fma2(acc[i][3], ai, bv3);
    }
}

__device__ __forceinline__ void unpack_acc(ull acc[8][4], float outv[8][8]) {
#pragma unroll
    for (int i = 0; i < 8; i++)
#pragma unroll
        for (int j2 = 0; j2 < 4; j2++) {
            float2 u = up2(acc[i][j2]);
            outv[i][2*j2]   = u.x;
            outv[i][2*j2+1] = u.y;
        }
}

// ---------------------------------------------------------------------------
// 0: zero accumulators (must run every launch: graph replays reuse globals)
// ---------------------------------------------------------------------------
__global__ void k_zero() {
    int t = threadIdx.x;
    if (t < HDIM) {
        g_bn1_sum[0][t] = 0.f; g_bn1_sum[1][t] = 0.f;
        g_bn1_sq[0][t]  = 0.f; g_bn1_sq[1][t]  = 0.f;
        g_bn2_sum[0][t] = 0.f; g_bn2_sum[1][t] = 0.f;
        g_bn2_sq[0][t]  = 0.f; g_bn2_sq[1][t]  = 0.f;
        g_bnF_sum[t]    = 0.f; g_bnF_sq[t]     = 0.f;
    }
}

// ---------------------------------------------------------------------------
// 1: per-node squared norms (one warp per node)
// ---------------------------------------------------------------------------
__global__ void k_sq(const float* __restrict__ x) {
    int w    = (blockIdx.x * blockDim.x + threadIdx.x) >> 5;
    int lane = threadIdx.x & 31;
    if (w >= NT) return;
    float v0 = x[(size_t)w * CDIM + lane];
    float v1 = x[(size_t)w * CDIM + 32 + lane];
    float s = v0 * v0 + v1 * v1;
#pragma unroll
    for (int off = 16; off; off >>= 1) s += __shfl_xor_sync(0xffffffffu, s, off);
    if (lane == 0) g_sq[w] = s;
}

// ---------------------------------------------------------------------------
// 2: pairwise squared distances per batch (128x128x64 tiles)
// ---------------------------------------------------------------------------
__global__ __launch_bounds__(256) void k_d2(const float* __restrict__ x) {
    __shared__ float Ai[32][LDW];
    __shared__ float Aj[32][LDW];
    const int b  = blockIdx.z;
    const int i0 = blockIdx.y * 128, j0 = blockIdx.x * 128;
    const float* X = x + (size_t)b * NNODE * CDIM;
    const int tid = threadIdx.x, ty = tid >> 4, tx = tid & 15;
    ull acc[8][4];
#pragma unroll
    for (int i = 0; i < 8; i++)
#pragma unroll
        for (int j = 0; j < 4; j++) acc[i][j] = 0ull;

    for (int kc = 0; kc < CDIM; kc += 32) {
        __syncthreads();
        for (int idx = tid; idx < 128 * 32; idx += 256) {
            int row = idx >> 5, kk = idx & 31;
            Ai[kk][row] = X[(size_t)(i0 + row) * CDIM + kc + kk];
            Aj[kk][row] = X[(size_t)(j0 + row) * CDIM + kc + kk];
        }
        __syncthreads();
#pragma unroll 8
        for (int kk = 0; kk < 32; kk++)
            micro_step(&Ai[kk][0], &Aj[kk][0], ty * 8, tx * 8, acc);
    }
    float outv[8][8];
    unpack_acc(acc, outv);
    float sqi[8], sqj[8];
#pragma unroll
    for (int i = 0; i < 8; i++) sqi[i] = g_sq[b * NNODE + i0 + ty * 8 + i];
#pragma unroll
    for (int j = 0; j < 8; j++) sqj[j] = g_sq[b * NNODE + j0 + tx * 8 + j];
#pragma unroll
    for (int i = 0; i < 8; i++) {
        size_t row = ((size_t)(b * NNODE + i0 + ty * 8 + i)) * NNODE + j0 + tx * 8;
        float v[8];
#pragma unroll
        for (int j = 0; j < 8; j++) v[j] = sqi[i] + sqj[j] - 2.f * outv[i][j];
        *(float4*)&g_d2[row]     = make_float4(v[0], v[1], v[2], v[3]);
        *(float4*)&g_d2[row + 4] = make_float4(v[4], v[5], v[6], v[7]);
    }
}

// ---------------------------------------------------------------------------
// 3: top-K smallest per row (block per row, 16x iterative argmin)
// ---------------------------------------------------------------------------
__global__ void k_topk() {
    __shared__ float vals[NNODE];
    __shared__ float wmin[8];
    __shared__ int   warg[8];
    const size_t row = (size_t)blockIdx.x * NNODE;
    const int tid = threadIdx.x;
    for (int j = tid; j < NNODE; j += 256) vals[j] = g_d2[row + j];
    __syncthreads();
    const int b = blockIdx.x >> 11;   // NNODE = 2048
    for (int k = 0; k < KNEIGH; k++) {
        float bv = 3.0e38f; int bi = 0;
        for (int j = tid; j < NNODE; j += 256) {
            float v = vals[j];
            if (v < bv) { bv = v; bi = j; }
        }
#pragma unroll
        for (int off = 16; off; off >>= 1) {
            float ov = __shfl_down_sync(0xffffffffu, bv, off);
            int   oi = __shfl_down_sync(0xffffffffu, bi, off);
            if (ov < bv || (ov == bv && oi < bi)) { bv = ov; bi = oi; }
        }
        if ((tid & 31) == 0) { wmin[tid >> 5] = bv; warg[tid >> 5] = bi; }
        __syncthreads();
        if (tid == 0) {
            float fb = wmin[0]; int fi = warg[0];
            for (int w = 1; w < 8; w++)
                if (wmin[w] < fb || (wmin[w] == fb && warg[w] < fi)) { fb = wmin[w]; fi = warg[w]; }
            g_idx[(size_t)blockIdx.x * KNEIGH + k] = b * NNODE + fi;
            vals[fi] = 3.0e38f;
        }
        __syncthreads();
    }
}

// ---------------------------------------------------------------------------
// 4: p/q GEMMs. z: 0=s/p, 1=s/q, 2=t/p, 3=t/q
// ---------------------------------------------------------------------------
__global__ __launch_bounds__(256) void k_pq(const float* __restrict__ x,
                                            const float* __restrict__ sW1, const float* __restrict__ sb1,
                                            const float* __restrict__ tW1, const float* __restrict__ tb1) {
    __shared__ float Xs[32][LDW];
    __shared__ float Ws[32][LDW];
    const int z   = blockIdx.z;
    const int st  = z >> 1;
    const bool isP = (z & 1) == 0;
    const float* W1 = st ? tW1 : sW1;
    const float* B1 = st ? tb1 : sb1;
    const int n0 = blockIdx.x * 128;
    const int tid = threadIdx.x, ty = tid >> 4, tx = tid & 15;
    ull acc[8][4];
#pragma unroll
    for (int i = 0; i < 8; i++)
#pragma unroll
        for (int j = 0; j < 4; j++) acc[i][j] = 0ull;

    for (int kc = 0; kc < CDIM; kc += 32) {
        __syncthreads();
        for (int idx = tid; idx < 128 * 32; idx += 256) {
            int r = idx >> 5, kk = idx & 31;
            Xs[kk][r] = x[(size_t)(n0 + r) * CDIM + kc + kk];
        }
        for (int idx = tid; idx < 32 * HDIM; idx += 256) {
            int kk = idx >> 7, col = idx & 127;
            int kr = kc + kk;
            float w = W1[(size_t)(CDIM + kr) * HDIM + col];
            if (isP) w = W1[(size_t)kr * HDIM + col] - w;
            Ws[kk][col] = w;
        }
        __syncthreads();
#pragma unroll 8
        for (int kk = 0; kk < 32; kk++)
            micro_step(&Xs[kk][0], &Ws[kk][0], ty * 8, tx * 8, acc);
    }
    float outv[8][8];
    unpack_acc(acc, outv);
    float* O = isP ? g_p[st] : g_q[st];
    float bj[8];
#pragma unroll
    for (int j = 0; j < 8; j++) bj[j] = isP ? B1[tx * 8 + j] : 0.f;
#pragma unroll
    for (int i = 0; i < 8; i++) {
        size_t row = (size_t)(n0 + ty * 8 + i) * HDIM + tx * 8;
        *(float4*)&O[row]     = make_float4(outv[i][0] + bj[0], outv[i][1] + bj[1],
                                            outv[i][2] + bj[2], outv[i][3] + bj[3]);
        *(float4*)&O[row + 4] = make_float4(outv[i][4] + bj[4], outv[i][5] + bj[5],
                                            outv[i][6] + bj[6], outv[i][7] + bj[7]);
    }
}

// ---------------------------------------------------------------------------
// 5: BN1 statistics over all edges, both streams (h1 = p[n] + q[j])
// ---------------------------------------------------------------------------
__global__ void k_bn1stats() {
    const int h = threadIdx.x;          // 128 threads = channels
    const int node0 = blockIdx.x * 32;  // 1024 blocks x 32 nodes
    float s0 = 0.f, q0 = 0.f, s1 = 0.f, q1 = 0.f;
    for (int nl = 0; nl < 32; nl++) {
        int n = node0 + nl;
        float p0 = g_p[0][(size_t)n * HDIM + h];
        float p1 = g_p[1][(size_t)n * HDIM + h];
        for (int k = 0; k < KNEIGH; k++) {
            int j = g_idx[(size_t)n * KNEIGH + k];
            float a = p0 + g_q[0][(size_t)j * HDIM + h];
            float b = p1 + g_q[1][(size_t)j * HDIM + h];
            s0 += a; q0 += a * a;
            s1 += b; q1 += b * b;
        }
    }
    atomicAdd(&g_bn1_sum[0][h], s0); atomicAdd(&g_bn1_sq[0][h], q0);
    atomicAdd(&g_bn1_sum[1][h], s1); atomicAdd(&g_bn1_sq[1][h], q1);
}

// ---------------------------------------------------------------------------
// 6: BN finalize -> per-channel affine (a, c). which: 0=bn1, 1=bn2, 2=bnF
// ---------------------------------------------------------------------------
__global__ void k_bnfin(int which, int st, const float* __restrict__ g,
                        const float* __restrict__ be, float invN) {
    int h = threadIdx.x;
    float s, q;
    if (which == 0)      { s = g_bn1_sum[st][h]; q = g_bn1_sq[st][h]; }
    else if (which == 1) { s = g_bn2_sum[st][h]; q = g_bn2_sq[st][h]; }
    else                 { s = g_bnF_sum[h];     q = g_bnF_sq[h]; }
    float m   = s * invN;
    float var = fmaxf(q * invN - m * m, 0.f);
    float a   = g[h] * rsqrtf(var + BN_EPS);
    float c   = be[h] - m * a;
    if (which == 0)      { g_a1[st][h] = a; g_c1[st][h] = c; }
    else if (which == 1) { g_a2[st][h] = a; g_c2[st][h] = c; }
    else                 { g_aF[h] = a;     g_cF[h] = c; }
}

// ---------------------------------------------------------------------------
// 7: edge GEMM: z = relu(bn1(h1)), h2 = z @ W2 + b2; emits per-node max/min
//    over K and per-channel sum/sumsq (BN2 stats). Block: 8 nodes x 16 edges
//    = 128 edge-rows x 128 out-cols, K=128.
// ---------------------------------------------------------------------------
__global__ __launch_bounds__(256) void k_edge(const float* __restrict__ sW2, const float* __restrict__ sb2,
                                              const float* __restrict__ tW2, const float* __restrict__ tb2) {
    __shared__ float Zs[32][LDW];
    __shared__ float Ws[32][LDW];
    __shared__ int   sidx[128];
    __shared__ float s_sum[HDIM], s_sq[HDIM];
    const int st = blockIdx.z;
    const float* W2 = st ? tW2 : sW2;
    const float* B2 = st ? tb2 : sb2;
    const float* P  = g_p[st];
    const float* Q  = g_q[st];
    const float* A1 = g_a1[st];
    const float* C1 = g_c1[st];
    const int node0 = blockIdx.x * 8;
    const int tid = threadIdx.x, ty = tid >> 4, tx = tid & 15;
    if (tid < 128) {
        sidx[tid]  = g_idx[(size_t)node0 * KNEIGH + tid];
        s_sum[tid] = 0.f;
        s_sq[tid]  = 0.f;
    }
    ull acc[8][4];
#pragma unroll
    for (int i = 0; i < 8; i++)
#pragma unroll
        for (int j = 0; j < 4; j++) acc[i][j] = 0ull;

    for (int kc = 0; kc < HDIM; kc += 32) {
        __syncthreads();
        for (int idx = tid; idx < 128 * 32; idx += 256) {
            int e = idx >> 5, kk = idx & 31;
            int ch = kc + kk;
            int n = node0 + (e >> 4);
            int j = sidx[e];
            float hv = P[(size_t)n * HDIM + ch] + Q[(size_t)j * HDIM + ch];
            Zs[kk][e] = fmaxf(fmaf(A1[ch], hv, C1[ch]), 0.f);
        }
        for (int idx = tid; idx < 32 * HDIM; idx += 256) {
            int kk = idx >> 7, col = idx & 127;
            Ws[kk][col] = W2[(size_t)(kc + kk) * HDIM + col];
        }
        __syncthreads();
#pragma unroll 8
        for (int kk = 0; kk < 32; kk++)
            micro_step(&Zs[kk][0], &Ws[kk][0], ty * 8, tx * 8, acc);
    }
    float outv[8][8];
    unpack_acc(acc, outv);
    float bj[8];
#pragma unroll
    for (int j = 0; j < 8; j++) bj[j] = B2[tx * 8 + j];
#pragma unroll
    for (int j = 0; j < 8; j++) {
        float cs = 0.f, cq = 0.f, cmx = -3.0e38f, cmn = 3.0e38f;
#pragma unroll
        for (int i = 0; i < 8; i++) {
            float v = outv[i][j] + bj[j];
            cs += v; cq += v * v;
            cmx = fmaxf(cmx, v); cmn = fminf(cmn, v);
        }
        // combine the two ty-halves of each 16-edge node group (lanes 16 apart)
        cs  += __shfl_xor_sync(0xffffffffu, cs, 16);
        cq  += __shfl_xor_sync(0xffffffffu, cq, 16);
        cmx  = fmaxf(cmx, __shfl_xor_sync(0xffffffffu, cmx, 16));
        cmn  = fminf(cmn, __shfl_xor_sync(0xffffffffu, cmn, 16));
        if ((ty & 1) == 0) {
            int node = node0 + (ty >> 1);
            int col  = tx * 8 + j;
            g_aggmax[st][(size_t)node * HDIM + col] = cmx;
            g_aggmin[st][(size_t)node * HDIM + col] = cmn;
            atomicAdd(&s_sum[col], cs);
            atomicAdd(&s_sq[col], cq);
        }
    }
    __syncthreads();
    if (tid < HDIM) {
        atomicAdd(&g_bn2_sum[st][tid], s_sum[tid]);
        atomicAdd(&g_bn2_sq[st][tid], s_sq[tid]);
    }
}

// ---------------------------------------------------------------------------
// 8: final GEMM: comb (NTx256, built on the fly from aggregates) @ f_W + f_b
//    writes hF and accumulates BN-F stats.
// ---------------------------------------------------------------------------
__global__ __launch_bounds__(256) void k_final(const float* __restrict__ fW, const float* __restrict__ fb) {
    __shared__ float Fs[32][LDW];
    __shared__ float Ws[32][LDW];
    __shared__ float s_sum[HDIM], s_sq[HDIM];
    const int n0 = blockIdx.x * 128;
    const int tid = threadIdx.x, ty = tid >> 4, tx = tid & 15;
    if (tid < 128) { s_sum[tid] = 0.f; s_sq[tid] = 0.f; }
    ull acc[8][4];
#pragma unroll
    for (int i = 0; i < 8; i++)
#pragma unroll
        for (int j = 0; j < 4; j++) acc[i][j] = 0ull;

    for (int kc = 0; kc < 2 * HDIM; kc += 32) {
        __syncthreads();
        for (int idx = tid; idx < 128 * 32; idx += 256) {
            int nl = idx >> 5, kk = idx & 31;
            int kf = kc + kk;
            int st = kf >> 7, ch = kf & 127;
            float a2 = g_a2[st][ch], c2 = g_c2[st][ch];
            size_t o = (size_t)(n0 + nl) * HDIM + ch;
            float v = (a2 >= 0.f) ? g_aggmax[st][o] : g_aggmin[st][o];
            Fs[kk][nl] = fmaxf(fmaf(a2, v, c2), 0.f);
        }
        for (int idx = tid; idx < 32 * HDIM; idx += 256) {
            int kk = idx >> 7, col = idx & 127;
            Ws[kk][col] = fW[(size_t)(kc + kk) * HDIM + col];
        }
        __syncthreads();
#pragma unroll 8
        for (int kk = 0; kk < 32; kk++)
            micro_step(&Fs[kk][0], &Ws[kk][0], ty * 8, tx * 8, acc);
    }
    float outv[8][8];
    unpack_acc(acc, outv);
    float bj[8];
#pragma unroll
    for (int j = 0; j < 8; j++) bj[j] = fb[tx * 8 + j];
#pragma unroll
    for (int i = 0; i < 8; i++)
#pragma unroll
        for (int j = 0; j < 8; j++) outv[i][j] += bj[j];
#pragma unroll
    for (int i = 0; i < 8; i++) {
        size_t row = (size_t)(n0 + ty * 8 + i) * HDIM + tx * 8;
        *(float4*)&g_hF[row]     = make_float4(outv[i][0], outv[i][1], outv[i][2], outv[i][3]);
        *(float4*)&g_hF[row + 4] = make_float4(outv[i][4], outv[i][5], outv[i][6], outv[i][7]);
    }
#pragma unroll
    for (int j = 0; j < 8; j++) {
        float cs = 0.f, cq = 0.f;
#pragma unroll
        for (int i = 0; i < 8; i++) { float v = outv[i][j]; cs += v; cq += v * v; }
        cs += __shfl_xor_sync(0xffffffffu, cs, 16);
        cq += __shfl_xor_sync(0xffffffffu, cq, 16);
        if ((ty & 1) == 0) {
            int col = tx * 8 + j;
            atomicAdd(&s_sum[col], cs);
            atomicAdd(&s_sq[col], cq);
        }
    }
    __syncthreads();
    if (tid < HDIM) {
        atomicAdd(&g_bnF_sum[tid], s_sum[tid]);
        atomicAdd(&g_bnF_sq[tid], s_sq[tid]);
    }
}

// ---------------------------------------------------------------------------
// 9: output elementwise: relu(aF*hF + cF)
// ---------------------------------------------------------------------------
__global__ void k_out(float* __restrict__ out) {
    int idx = blockIdx.x * 256 + threadIdx.x;
    int col = idx & 127;
    out[idx] = fmaxf(fmaf(g_aF[col], g_hF[idx], g_cF[col]), 0.f);
}

// ---------------------------------------------------------------------------
// launcher
// ---------------------------------------------------------------------------
extern "C" void kernel_launch(void* const* d_in, const int* in_sizes, int n_in,
                              void* d_out, int out_size) {
    (void)in_sizes; (void)n_in; (void)out_size;
    const float* x     = (const float*)d_in[0];
    // d_in[1] = batch (unused: sorted, equal-size graphs)
    const float* s_W1  = (const float*)d_in[2];
    const float* s_b1  = (const float*)d_in[3];
    const float* s_g1  = (const float*)d_in[4];
    const float* s_be1 = (const float*)d_in[5];
    const float* s_W2  = (const float*)d_in[6];
    const float* s_b2  = (const float*)d_in[7];
    const float* s_g2  = (const float*)d_in[8];
    const float* s_be2 = (const float*)d_in[9];
    const float* t_W1  = (const float*)d_in[10];
    const float* t_b1  = (const float*)d_in[11];
    const float* t_g1  = (const float*)d_in[12];
    const float* t_be1 = (const float*)d_in[13];
    const float* t_W2  = (const float*)d_in[14];
    const float* t_b2  = (const float*)d_in[15];
    const float* t_g2  = (const float*)d_in[16];
    const float* t_be2 = (const float*)d_in[17];
    const float* f_W   = (const float*)d_in[18];
    const float* f_b   = (const float*)d_in[19];
    const float* f_g   = (const float*)d_in[20];
    const float* f_be  = (const float*)d_in[21];
    float* out = (float*)d_out;

    const float invE  = 1.f / (float)EDGES;
    const float invNT = 1.f / (float)NT;

    k_zero<<<1, 128>>>();
    k_sq<<<NT / 8, 256>>>(x);
    k_d2<<<dim3(NNODE / 128, NNODE / 128, BBATCH), 256>>>(x);
    k_topk<<<NT, 256>>>();
    k_pq<<<dim3(NT / 128, 1, 4), 256>>>(x, s_W1, s_b1, t_W1, t_b1);
    k_bn1stats<<<NT / 32, 128>>>();
    k_bnfin<<<1, 128>>>(0, 0, s_g1, s_be1, invE);
    k_bnfin<<<1, 128>>>(0, 1, t_g1, t_be1, invE);
    k_edge<<<dim3(NT / 8, 1, 2), 256>>>(s_W2, s_b2, t_W2, t_b2);
    k_bnfin<<<1, 128>>>(1, 0, s_g2, s_be2, invE);
    k_bnfin<<<1, 128>>>(1, 1, t_g2, t_be2, invE);
    k_final<<<NT / 128, 256>>>(f_W, f_b);
    k_bnfin<<<1, 128>>>(2, 0, f_g, f_be, invNT);
    k_out<<<(NT * HDIM) / 256, 256>>>(out);
}